// round 6
// baseline (speedup 1.0000x reference)
#include <cuda_runtime.h>
#include <cuda_bf16.h>
#include <cstdint>

#define NN   50000
#define EE   800000
#define INF  128
#define HF   128
#define RR   8
#define OUTF 2
#define BN_EPS 1e-5f
#define GEMM_TILES ((NN + 127) / 128)   // 391
#define SCAT_BLOCKS 16384               // 131072 warps >= per-rel edge count

// ---------------- scratch (device globals; no allocation allowed) ----------
__device__ float g_xwbuf[(size_t)NN * HF];          // recycled per-relation xw
__device__ float g_agg[(size_t)NN * HF];            // layer accumulator
__device__ __nv_bfloat16 g_xhi[(size_t)NN * HF];    // bf16 hi split of acts
__device__ __nv_bfloat16 g_xlo[(size_t)NN * HF];    // bf16 lo split
__device__ __nv_bfloat16 g_whi[9 * 128 * 128];      // [mat][n][k] W^T, hi
__device__ __nv_bfloat16 g_wlo[9 * 128 * 128];      // lo
__device__ int   g_deg[NN * RR];
__device__ float g_sum[HF];
__device__ float g_sumsq[HF];
// edge bucketing (by relation type)
__device__ int   g_tcnt[RR];
__device__ int   g_tcur[RR];
__device__ int   g_tbase[RR + 1];
__device__ int   g_epack[EE];       // src | (type<<16)
__device__ int   g_etgt[EE];

// ======================= small helpers ======================================
__device__ __forceinline__ uint32_t smem_to_u32(const void* p) {
    uint32_t a;
    asm("{ .reg .u64 t; cvta.to.shared.u64 t, %1; cvt.u32.u64 %0, t; }"
        : "=r"(a) : "l"(p));
    return a;
}
__device__ __forceinline__ void cp16(uint32_t dst, const void* src) {
    asm volatile("cp.async.cg.shared.global [%0], [%1], 16;"
                 :: "r"(dst), "l"(__cvta_generic_to_global(src)));
}
__device__ __forceinline__ void mma_bf16(float d[4], const uint32_t a[4],
                                         const uint32_t b[2]) {
    asm volatile(
        "mma.sync.aligned.m16n8k16.row.col.f32.bf16.bf16.f32 "
        "{%0,%1,%2,%3}, {%4,%5,%6,%7}, {%8,%9}, {%0,%1,%2,%3};"
        : "+f"(d[0]), "+f"(d[1]), "+f"(d[2]), "+f"(d[3])
        : "r"(a[0]), "r"(a[1]), "r"(a[2]), "r"(a[3]), "r"(b[0]), "r"(b[1]));
}

// =============== SMEM layout (u32 units), stride 68 u32 = 136 bf16 ==========
#define SWU    68
#define AH_U   0
#define AL_U   (128 * SWU)                 // 8704
#define BH_U   (2 * 128 * SWU)             // 17408
#define BL_U   (BH_U + 128 * SWU)          // 26112
#define SMEM_U32S   (BL_U + 128 * SWU)     // 34816
#define SMEM_BYTES  (SMEM_U32S * 4)        // 139264

// prefetch one 128x128 bf16 tile (row-major [n][k]) into padded smem
__device__ __forceinline__ void prefetch_B(uint32_t sb, int bofs_u,
                                           const __nv_bfloat16* W) {
    int tid = threadIdx.x;
#pragma unroll
    for (int i = 0; i < 8; i++) {
        int e = i * 256 + tid;            // 0..2047 uint4s
        int row = e >> 4;                 // 0..127
        int q   = e & 15;                 // uint4 (8 bf16) within row
        cp16(sb + (uint32_t)(bofs_u + row * SWU + q * 4) * 4, W + row * 128 + q * 8);
    }
}

// one bf16 pass: D += A(smem,[m][k]) x B(smem,[n][k])^T over K=128
__device__ __forceinline__ void do_pass(const uint32_t* __restrict__ As,
                                        const uint32_t* __restrict__ Bs,
                                        float d[4][4][4], int wm, int wn,
                                        int lr, int lc) {
#pragma unroll
    for (int ks = 0; ks < 8; ks++) {
        int k0 = ks * 8;                  // u32 offset for k = ks*16
        uint32_t a[4][4], b[4][2];
#pragma unroll
        for (int mt = 0; mt < 4; mt++) {
            const uint32_t* p = As + (wm * 64 + mt * 16 + lr) * SWU + k0 + lc;
            a[mt][0] = p[0];
            a[mt][1] = p[8 * SWU];
            a[mt][2] = p[4];
            a[mt][3] = p[8 * SWU + 4];
        }
#pragma unroll
        for (int nt = 0; nt < 4; nt++) {
            const uint32_t* p = Bs + (wn * 32 + nt * 8 + lr) * SWU + k0 + lc;
            b[nt][0] = p[0];
            b[nt][1] = p[4];
        }
#pragma unroll
        for (int mt = 0; mt < 4; mt++)
#pragma unroll
            for (int nt = 0; nt < 4; nt++) mma_bf16(d[mt][nt], a[mt], b[nt]);
    }
}

// ================== single-matrix bf16 GEMM, 3-term split ===================
// D[m,n] = sum_k A[m,k]*B[n,k]; mat<8 -> g_xwbuf; mat==8 -> g_agg (+bias).
__global__ void __launch_bounds__(256, 1) gemm_one_kernel(int mat,
                                                          const float* __restrict__ bias) {
    extern __shared__ uint32_t smu[];
    uint32_t sb = smem_to_u32(smu);
    const int tid = threadIdx.x;
    const int wid = tid >> 5, lane = tid & 31;
    const int wm = wid & 1, wn = wid >> 1;       // 2 x 4 warp grid (64x32 tiles)
    const int lr = lane >> 2, lc = lane & 3;
    const int m0 = blockIdx.x * 128;

    // A tiles (hi/lo); zero rows past NN
#pragma unroll
    for (int i = 0; i < 8; i++) {
        int e = i * 256 + tid;
        int row = e >> 4, q = e & 15;
        uint32_t dh = sb + (uint32_t)(AH_U + row * SWU + q * 4) * 4;
        uint32_t dl = sb + (uint32_t)(AL_U + row * SWU + q * 4) * 4;
        if (m0 + row < NN) {
            cp16(dh, g_xhi + (size_t)(m0 + row) * 128 + q * 8);
            cp16(dl, g_xlo + (size_t)(m0 + row) * 128 + q * 8);
        } else {
            uint4 z = make_uint4(0, 0, 0, 0);
            *reinterpret_cast<uint4*>(smu + AH_U + row * SWU + q * 4) = z;
            *reinterpret_cast<uint4*>(smu + AL_U + row * SWU + q * 4) = z;
        }
    }
    prefetch_B(sb, BH_U, g_whi + mat * 16384);
    prefetch_B(sb, BL_U, g_wlo + mat * 16384);
    asm volatile("cp.async.commit_group;" ::: "memory");
    asm volatile("cp.async.wait_group 0;" ::: "memory");
    __syncthreads();

    float d[4][4][4];
#pragma unroll
    for (int mt = 0; mt < 4; mt++)
#pragma unroll
        for (int nt = 0; nt < 4; nt++)
#pragma unroll
            for (int j = 0; j < 4; j++) d[mt][nt][j] = 0.f;

    const uint32_t* Ah = smu + AH_U;
    const uint32_t* Al = smu + AL_U;
    const uint32_t* Bh = smu + BH_U;
    const uint32_t* Bl = smu + BL_U;
    do_pass(Ah, Bh, d, wm, wn, lr, lc);   // hi*hi
    do_pass(Al, Bh, d, wm, wn, lr, lc);   // lo*hi
    do_pass(Ah, Bl, d, wm, wn, lr, lc);   // hi*lo

    float* gbase = (mat < 8) ? g_xwbuf : g_agg;
#pragma unroll
    for (int mt = 0; mt < 4; mt++) {
        int r0 = m0 + wm * 64 + mt * 16 + lr;
#pragma unroll
        for (int nt = 0; nt < 4; nt++) {
            int col = wn * 32 + nt * 8 + lc * 2;
            float b0 = 0.f, b1 = 0.f;
            if (mat == 8) { b0 = bias[col]; b1 = bias[col + 1]; }
            if (r0 < NN)
                *reinterpret_cast<float2*>(gbase + (size_t)r0 * HF + col) =
                    make_float2(d[mt][nt][0] + b0, d[mt][nt][1] + b1);
            if (r0 + 8 < NN)
                *reinterpret_cast<float2*>(gbase + (size_t)(r0 + 8) * HF + col) =
                    make_float2(d[mt][nt][2] + b0, d[mt][nt][3] + b1);
        }
    }
}

// ======================= prep kernels ========================================
__global__ void split_x_kernel(const float* __restrict__ x_in) {
    size_t idx = (size_t)blockIdx.x * blockDim.x + threadIdx.x;
    if (idx >= (size_t)NN * HF) return;
    float v = x_in[idx];
    __nv_bfloat16 h = __float2bfloat16_rn(v);
    g_xhi[idx] = h;
    g_xlo[idx] = __float2bfloat16_rn(v - __bfloat162float(h));
}

// transpose W[mat][k][n] -> [mat][n][k], split hi/lo bf16. mat 8 = root.
__global__ void split_w_kernel(const float* __restrict__ w, const float* __restrict__ root) {
    int idx = blockIdx.x * blockDim.x + threadIdx.x;
    if (idx >= 9 * 16384) return;
    int mat = idx >> 14;
    int n = (idx >> 7) & 127;
    int k = idx & 127;
    float v = (mat < 8) ? w[(mat << 14) + (k << 7) + n] : root[(k << 7) + n];
    __nv_bfloat16 h = __float2bfloat16_rn(v);
    g_whi[idx] = h;
    g_wlo[idx] = __float2bfloat16_rn(v - __bfloat162float(h));
}

// ======================= graph preprocessing =================================
__global__ void zero_deg_sums_kernel() {
    int idx = blockIdx.x * blockDim.x + threadIdx.x;
    if (idx < NN * RR) g_deg[idx] = 0;
    if (idx < HF) { g_sum[idx] = 0.f; g_sumsq[idx] = 0.f; }
    if (idx < RR) g_tcnt[idx] = 0;
}
__global__ void zero_sums_kernel() {
    int idx = threadIdx.x;
    if (idx < HF) { g_sum[idx] = 0.f; g_sumsq[idx] = 0.f; }
}
// per-(node,rel) degree + block-aggregated type histogram
__global__ void deg_count_kernel(const int* __restrict__ ei, const int* __restrict__ et) {
    __shared__ int hcnt[RR];
    int tid = threadIdx.x;
    if (tid < RR) hcnt[tid] = 0;
    __syncthreads();
    int e = blockIdx.x * blockDim.x + tid;
    if (e < EE) {
        int tgt = ei[EE + e];
        int t   = et[e];
        atomicAdd(&g_deg[tgt * RR + t], 1);
        atomicAdd(&hcnt[t], 1);
    }
    __syncthreads();
    if (tid < RR && hcnt[tid] > 0) atomicAdd(&g_tcnt[tid], hcnt[tid]);
}
__global__ void prefix_kernel() {
    if (threadIdx.x == 0) {
        int acc = 0;
        for (int r = 0; r < RR; r++) {
            g_tbase[r] = acc;
            g_tcur[r]  = acc;
            acc += g_tcnt[r];
        }
        g_tbase[RR] = acc;
    }
}
// block-aggregated placement: SMEM rank + one range reservation per type/blk
__global__ void place_kernel(const int* __restrict__ ei, const int* __restrict__ et) {
    __shared__ int scnt[RR], sbase[RR];
    int tid = threadIdx.x;
    if (tid < RR) scnt[tid] = 0;
    __syncthreads();
    int e = blockIdx.x * blockDim.x + tid;
    int rank = 0, t = 0, src = 0, tgt = 0;
    bool valid = (e < EE);
    if (valid) {
        src = ei[e];
        tgt = ei[EE + e];
        t   = et[e];
        rank = atomicAdd(&scnt[t], 1);
    }
    __syncthreads();
    if (tid < RR) sbase[tid] = (scnt[tid] > 0) ? atomicAdd(&g_tcur[tid], scnt[tid]) : 0;
    __syncthreads();
    if (valid) {
        int pos = sbase[t] + rank;
        g_epack[pos] = src | (t << 16);
        g_etgt[pos]  = tgt;
    }
}

// ------- per-relation scatter: warp per edge, gathers from L2-hot xwbuf ------
__global__ void scatter_rel_kernel(int rel) {
    int base = g_tbase[rel], end = g_tbase[rel + 1];
    int w = base + ((blockIdx.x * blockDim.x + threadIdx.x) >> 5);
    if (w >= end) return;
    int lane = threadIdx.x & 31;
    int src = g_epack[w] & 0xFFFF;
    int tgt = g_etgt[w];
    float inv = 1.0f / (float)g_deg[tgt * RR + rel];
    float4 v = *reinterpret_cast<const float4*>(
        g_xwbuf + (size_t)src * HF + lane * 4);
    float* dst = g_agg + (size_t)tgt * HF + lane * 4;
    asm volatile("red.global.add.v4.f32 [%0], {%1, %2, %3, %4};"
        :: "l"(__cvta_generic_to_global(dst)),
           "f"(v.x * inv), "f"(v.y * inv), "f"(v.z * inv), "f"(v.w * inv)
        : "memory");
}

// ---------------- BN stats / apply ------------------------------------------
__global__ void bn_stats_kernel() {
    int c = threadIdx.x & 127;
    int rstart = blockIdx.x * (blockDim.x >> 7) + (threadIdx.x >> 7);
    int rstep  = gridDim.x * (blockDim.x >> 7);
    float s = 0.f, ss = 0.f;
    for (int r = rstart; r < NN; r += rstep) {
        float v = g_agg[(size_t)r * HF + c];
        s += v;
        ss += v * v;
    }
    atomicAdd(&g_sum[c], s);
    atomicAdd(&g_sumsq[c], ss);
}
// BN + ReLU, emitting bf16 hi/lo splits (next GEMM A / classifier input)
__global__ void bn_apply_kernel(const float* __restrict__ gamma,
                                const float* __restrict__ beta) {
    int idx = blockIdx.x * blockDim.x + threadIdx.x;
    if (idx >= NN * HF) return;
    int c = idx & 127;
    const float invN = 1.0f / (float)NN;
    float mean = g_sum[c] * invN;
    float var  = fmaxf(g_sumsq[c] * invN - mean * mean, 0.f);
    float v = (g_agg[idx] - mean) * rsqrtf(var + BN_EPS) * gamma[c] + beta[c];
    v = fmaxf(v, 0.f);
    __nv_bfloat16 h = __float2bfloat16_rn(v);
    g_xhi[idx] = h;
    g_xlo[idx] = __float2bfloat16_rn(v - __bfloat162float(h));
}

// ---------------- classifier: out[N,2] = (hi+lo) @ cw + cb ------------------
__global__ void classifier_kernel(const float* __restrict__ cw,
                                  const float* __restrict__ cb,
                                  float* __restrict__ out) {
    __shared__ float wsm[HF * OUTF];
    if (threadIdx.x < HF * OUTF) wsm[threadIdx.x] = cw[threadIdx.x];
    __syncthreads();
    int w = (blockIdx.x * blockDim.x + threadIdx.x) >> 5;
    if (w >= NN) return;
    int lane = threadIdx.x & 31;
    const __nv_bfloat162* ph = reinterpret_cast<const __nv_bfloat162*>(
        g_xhi + (size_t)w * HF + lane * 4);
    const __nv_bfloat162* pl = reinterpret_cast<const __nv_bfloat162*>(
        g_xlo + (size_t)w * HF + lane * 4);
    __nv_bfloat162 h0 = ph[0], h1 = ph[1], l0 = pl[0], l1 = pl[1];
    float vx = __bfloat162float(h0.x) + __bfloat162float(l0.x);
    float vy = __bfloat162float(h0.y) + __bfloat162float(l0.y);
    float vz = __bfloat162float(h1.x) + __bfloat162float(l1.x);
    float vw = __bfloat162float(h1.y) + __bfloat162float(l1.y);
    int c = lane * 4;
    float o0 = vx * wsm[(c + 0) * 2]     + vy * wsm[(c + 1) * 2]
             + vz * wsm[(c + 2) * 2]     + vw * wsm[(c + 3) * 2];
    float o1 = vx * wsm[(c + 0) * 2 + 1] + vy * wsm[(c + 1) * 2 + 1]
             + vz * wsm[(c + 2) * 2 + 1] + vw * wsm[(c + 3) * 2 + 1];
#pragma unroll
    for (int off = 16; off > 0; off >>= 1) {
        o0 += __shfl_down_sync(0xFFFFFFFFu, o0, off);
        o1 += __shfl_down_sync(0xFFFFFFFFu, o1, off);
    }
    if (lane == 0) {
        out[(size_t)w * 2 + 0] = o0 + cb[0];
        out[(size_t)w * 2 + 1] = o1 + cb[1];
    }
}

// ================================ launch =====================================
extern "C" void kernel_launch(void* const* d_in, const int* in_sizes, int n_in,
                              void* d_out, int out_size) {
    const float* x    = (const float*)d_in[0];
    const int*   ei   = (const int*)d_in[1];
    const int*   et   = (const int*)d_in[2];
    const float* w1   = (const float*)d_in[3];
    const float* r1   = (const float*)d_in[4];
    const float* b1   = (const float*)d_in[5];
    const float* g1   = (const float*)d_in[6];
    const float* be1  = (const float*)d_in[7];
    const float* w2   = (const float*)d_in[8];
    const float* r2   = (const float*)d_in[9];
    const float* b2   = (const float*)d_in[10];
    const float* g2   = (const float*)d_in[11];
    const float* be2  = (const float*)d_in[12];
    const float* cw   = (const float*)d_in[13];
    const float* cb   = (const float*)d_in[14];
    float* out = (float*)d_out;

    cudaFuncSetAttribute(gemm_one_kernel,
                         cudaFuncAttributeMaxDynamicSharedMemorySize, SMEM_BYTES);

    int bn_apply_blocks = (NN * HF + 255) / 256;
    int cls_blocks      = (NN * 32 + 255) / 256;
    int splitx_blocks   = (NN * HF + 255) / 256;
    int splitw_blocks   = (9 * 16384 + 255) / 256;
    int edge_blocks     = (EE + 255) / 256;

    // ---- graph prep (shared by both layers) ----
    zero_deg_sums_kernel<<<(NN * RR + 255) / 256, 256>>>();
    deg_count_kernel<<<edge_blocks, 256>>>(ei, et);
    prefix_kernel<<<1, 32>>>();
    place_kernel<<<edge_blocks, 256>>>(ei, et);

    // ---- layer 1 ----
    split_w_kernel<<<splitw_blocks, 256>>>(w1, r1);
    split_x_kernel<<<splitx_blocks, 256>>>(x);
    gemm_one_kernel<<<GEMM_TILES, 256, SMEM_BYTES>>>(8, b1);   // root + bias -> agg
    for (int r = 0; r < RR; r++) {
        gemm_one_kernel<<<GEMM_TILES, 256, SMEM_BYTES>>>(r, b1);
        scatter_rel_kernel<<<SCAT_BLOCKS, 256>>>(r);
    }
    bn_stats_kernel<<<256, 256>>>();
    bn_apply_kernel<<<bn_apply_blocks, 256>>>(g1, be1);

    // ---- layer 2 (degree + buckets reused) ----
    zero_sums_kernel<<<1, 128>>>();
    split_w_kernel<<<splitw_blocks, 256>>>(w2, r2);
    gemm_one_kernel<<<GEMM_TILES, 256, SMEM_BYTES>>>(8, b2);
    for (int r = 0; r < RR; r++) {
        gemm_one_kernel<<<GEMM_TILES, 256, SMEM_BYTES>>>(r, b2);
        scatter_rel_kernel<<<SCAT_BLOCKS, 256>>>(r);
    }
    bn_stats_kernel<<<256, 256>>>();
    bn_apply_kernel<<<bn_apply_blocks, 256>>>(g2, be2);

    // ---- classifier ----
    classifier_kernel<<<cls_blocks, 256>>>(cw, cb, out);
}

// round 7
// speedup vs baseline: 1.1663x; 1.1663x over previous
#include <cuda_runtime.h>
#include <cuda_bf16.h>
#include <cstdint>

#define NN   50000
#define EE   800000
#define INF  128
#define HF   128
#define RR   8
#define OUTF 2
#define BN_EPS 1e-5f
#define GEMM_TILES ((NN + 127) / 128)   // 391
#define BINS (RR * NN)                  // 400000 (type,src) bins
#define SCAN_BLOCKS ((BINS + 1023) / 1024)  // 391

// ---------------- scratch (device globals; no allocation allowed) ----------
__device__ float g_xw[(size_t)RR * NN * HF];        // [R][N][H] transformed
__device__ float g_agg[(size_t)NN * HF];            // pre-BN layer output
__device__ __nv_bfloat16 g_xhi[(size_t)NN * HF];    // bf16 hi split of acts
__device__ __nv_bfloat16 g_xlo[(size_t)NN * HF];    // bf16 lo split
__device__ __nv_bfloat16 g_whi[9 * 128 * 128];      // [mat][n][k] W^T, hi
__device__ __nv_bfloat16 g_wlo[9 * 128 * 128];      // lo
__device__ int   g_deg[NN * RR];
__device__ float g_sum[HF];
__device__ float g_sumsq[HF];
// edge sorting by (type, src)
__device__ int   g_hist[BINS];      // per-bin counts
__device__ int   g_hcur[BINS];      // scan result -> running cursors
__device__ int   g_bsum[SCAN_BLOCKS];
__device__ int   g_epack[EE];       // src | (type<<16)
__device__ int   g_etgt[EE];

// ======================= small helpers ======================================
__device__ __forceinline__ uint32_t smem_to_u32(const void* p) {
    uint32_t a;
    asm("{ .reg .u64 t; cvta.to.shared.u64 t, %1; cvt.u32.u64 %0, t; }"
        : "=r"(a) : "l"(p));
    return a;
}
__device__ __forceinline__ void cp16(uint32_t dst, const void* src) {
    asm volatile("cp.async.cg.shared.global [%0], [%1], 16;"
                 :: "r"(dst), "l"(__cvta_generic_to_global(src)));
}
__device__ __forceinline__ void mma_bf16(float d[4], const uint32_t a[4],
                                         const uint32_t b[2]) {
    asm volatile(
        "mma.sync.aligned.m16n8k16.row.col.f32.bf16.bf16.f32 "
        "{%0,%1,%2,%3}, {%4,%5,%6,%7}, {%8,%9}, {%0,%1,%2,%3};"
        : "+f"(d[0]), "+f"(d[1]), "+f"(d[2]), "+f"(d[3])
        : "r"(a[0]), "r"(a[1]), "r"(a[2]), "r"(a[3]), "r"(b[0]), "r"(b[1]));
}

// =============== SMEM layout (u32 units), stride 68 u32 = 136 bf16 ==========
#define SWU    68
#define AH_U   0
#define AL_U   (128 * SWU)                 // 8704
#define B0_U   (2 * 128 * SWU)             // 17408
#define B1_U   (B0_U + 128 * SWU)          // 26112
#define SMEM_U32S   (B1_U + 128 * SWU)     // 34816
#define SMEM_BYTES  (SMEM_U32S * 4)        // 139264

// prefetch one 128x128 bf16 tile (row-major [n][k]) into padded smem
__device__ __forceinline__ void prefetch_B(uint32_t sb, int bofs_u,
                                           const __nv_bfloat16* W) {
    int tid = threadIdx.x;
#pragma unroll
    for (int i = 0; i < 8; i++) {
        int e = i * 256 + tid;            // 0..2047 uint4s
        int row = e >> 4;                 // 0..127
        int q   = e & 15;                 // uint4 (8 bf16) within row
        cp16(sb + (uint32_t)(bofs_u + row * SWU + q * 4) * 4, W + row * 128 + q * 8);
    }
}

// one bf16 pass: D += A(smem,[m][k]) x B(smem,[n][k])^T over K=128
__device__ __forceinline__ void do_pass(const uint32_t* __restrict__ As,
                                        const uint32_t* __restrict__ Bs,
                                        float d[4][4][4], int wm, int wn,
                                        int lr, int lc) {
#pragma unroll
    for (int ks = 0; ks < 8; ks++) {
        int k0 = ks * 8;                  // u32 offset for k = ks*16
        uint32_t a[4][4], b[4][2];
#pragma unroll
        for (int mt = 0; mt < 4; mt++) {
            const uint32_t* p = As + (wm * 64 + mt * 16 + lr) * SWU + k0 + lc;
            a[mt][0] = p[0];
            a[mt][1] = p[8 * SWU];
            a[mt][2] = p[4];
            a[mt][3] = p[8 * SWU + 4];
        }
#pragma unroll
        for (int nt = 0; nt < 4; nt++) {
            const uint32_t* p = Bs + (wn * 32 + nt * 8 + lr) * SWU + k0 + lc;
            b[nt][0] = p[0];
            b[nt][1] = p[4];
        }
#pragma unroll
        for (int mt = 0; mt < 4; mt++)
#pragma unroll
            for (int nt = 0; nt < 4; nt++) mma_bf16(d[mt][nt], a[mt], b[nt]);
    }
}

// ================== bf16 tensor GEMM: 9 matrices per M-tile =================
// D[m,n] = sum_k A[m,k]*B[n,k], 3-term bf16 (hi*hi + lo*hi + hi*lo).
// grid = 391 (128-row M tiles); 256 threads; mats 0..7 -> g_xw; 8 -> g_agg+bias.
__global__ void __launch_bounds__(256, 1) gemm_tc_kernel(const float* __restrict__ bias) {
    extern __shared__ uint32_t smu[];
    uint32_t sb = smem_to_u32(smu);
    const int tid = threadIdx.x;
    const int wid = tid >> 5, lane = tid & 31;
    const int wm = wid & 1, wn = wid >> 1;       // 2 x 4 warp grid (64x32 tiles)
    const int lr = lane >> 2, lc = lane & 3;
    const int m0 = blockIdx.x * 128;

    // A tiles (hi/lo) resident for whole CTA; zero rows past NN
#pragma unroll
    for (int i = 0; i < 8; i++) {
        int e = i * 256 + tid;
        int row = e >> 4, q = e & 15;
        uint32_t dh = sb + (uint32_t)(AH_U + row * SWU + q * 4) * 4;
        uint32_t dl = sb + (uint32_t)(AL_U + row * SWU + q * 4) * 4;
        if (m0 + row < NN) {
            cp16(dh, g_xhi + (size_t)(m0 + row) * 128 + q * 8);
            cp16(dl, g_xlo + (size_t)(m0 + row) * 128 + q * 8);
        } else {
            uint4 z = make_uint4(0, 0, 0, 0);
            *reinterpret_cast<uint4*>(smu + AH_U + row * SWU + q * 4) = z;
            *reinterpret_cast<uint4*>(smu + AL_U + row * SWU + q * 4) = z;
        }
    }
    prefetch_B(sb, B0_U, g_whi);    // B_hi(mat 0)
    asm volatile("cp.async.commit_group;" ::: "memory");
    asm volatile("cp.async.wait_group 0;" ::: "memory");
    __syncthreads();

    float d[4][4][4];
#pragma unroll
    for (int mt = 0; mt < 4; mt++)
#pragma unroll
        for (int nt = 0; nt < 4; nt++)
#pragma unroll
            for (int j = 0; j < 4; j++) d[mt][nt][j] = 0.f;

    const uint32_t* Ah = smu + AH_U;
    const uint32_t* Al = smu + AL_U;
    int stage = 0;
    // 18 tiles: even t = B_hi(t/2) [Ahi & Alo passes], odd t = B_lo(t/2) [Ahi pass]
    for (int t = 0; t < 18; t++) {
        if (t + 1 < 18) {
            int nm = (t + 1) >> 1;
            const __nv_bfloat16* Wn =
                ((t + 1) & 1) ? (g_wlo + nm * 16384) : (g_whi + nm * 16384);
            prefetch_B(sb, stage ? B0_U : B1_U, Wn);
        }
        asm volatile("cp.async.commit_group;" ::: "memory");

        const uint32_t* Bs = smu + (stage ? B1_U : B0_U);
        do_pass(Ah, Bs, d, wm, wn, lr, lc);               // a_hi x b
        if (!(t & 1)) do_pass(Al, Bs, d, wm, wn, lr, lc); // a_lo x b_hi

        if (t & 1) {
            int mat = t >> 1;
            float* gbase = (mat < 8) ? (g_xw + (size_t)mat * NN * HF) : g_agg;
#pragma unroll
            for (int mt = 0; mt < 4; mt++) {
                int r0 = m0 + wm * 64 + mt * 16 + lr;
#pragma unroll
                for (int nt = 0; nt < 4; nt++) {
                    int col = wn * 32 + nt * 8 + lc * 2;
                    float b0 = 0.f, b1 = 0.f;
                    if (mat == 8) { b0 = bias[col]; b1 = bias[col + 1]; }
                    if (r0 < NN)
                        *reinterpret_cast<float2*>(gbase + (size_t)r0 * HF + col) =
                            make_float2(d[mt][nt][0] + b0, d[mt][nt][1] + b1);
                    if (r0 + 8 < NN)
                        *reinterpret_cast<float2*>(gbase + (size_t)(r0 + 8) * HF + col) =
                            make_float2(d[mt][nt][2] + b0, d[mt][nt][3] + b1);
#pragma unroll
                    for (int j = 0; j < 4; j++) d[mt][nt][j] = 0.f;
                }
            }
        }
        asm volatile("cp.async.wait_group 0;" ::: "memory");
        __syncthreads();
        stage ^= 1;
    }
}

// ======================= prep kernels ========================================
__global__ void split_x_kernel(const float* __restrict__ x_in) {
    size_t idx = (size_t)blockIdx.x * blockDim.x + threadIdx.x;
    if (idx >= (size_t)NN * HF) return;
    float v = x_in[idx];
    __nv_bfloat16 h = __float2bfloat16_rn(v);
    g_xhi[idx] = h;
    g_xlo[idx] = __float2bfloat16_rn(v - __bfloat162float(h));
}

// transpose W[mat][k][n] -> [mat][n][k], split hi/lo bf16. mat 8 = root.
__global__ void split_w_kernel(const float* __restrict__ w, const float* __restrict__ root) {
    int idx = blockIdx.x * blockDim.x + threadIdx.x;
    if (idx >= 9 * 16384) return;
    int mat = idx >> 14;
    int n = (idx >> 7) & 127;
    int k = idx & 127;
    float v = (mat < 8) ? w[(mat << 14) + (k << 7) + n] : root[(k << 7) + n];
    __nv_bfloat16 h = __float2bfloat16_rn(v);
    g_whi[idx] = h;
    g_wlo[idx] = __float2bfloat16_rn(v - __bfloat162float(h));
}

// ======================= graph preprocessing =================================
__global__ void zero_prep_kernel() {
    int idx = blockIdx.x * blockDim.x + threadIdx.x;
    if (idx < NN * RR) g_deg[idx] = 0;
    if (idx < BINS) g_hist[idx] = 0;
    if (idx < HF) { g_sum[idx] = 0.f; g_sumsq[idx] = 0.f; }
}
__global__ void zero_sums_kernel() {
    int idx = threadIdx.x;
    if (idx < HF) { g_sum[idx] = 0.f; g_sumsq[idx] = 0.f; }
}
// per-(node,rel) degree + per-(type,src) histogram (both spread; low contention)
__global__ void deg_hist_kernel(const int* __restrict__ ei, const int* __restrict__ et) {
    int e = blockIdx.x * blockDim.x + threadIdx.x;
    if (e >= EE) return;
    int src = ei[e];
    int tgt = ei[EE + e];
    int t   = et[e];
    atomicAdd(&g_deg[tgt * RR + t], 1);
    atomicAdd(&g_hist[t * NN + src], 1);
}
// --- 3-step exclusive scan over g_hist (400000 bins) -> g_hcur ---------------
__global__ void scan1_kernel() {    // per-1024-bin block sums
    __shared__ int sh[256];
    int base = blockIdx.x * 1024;
    int t = threadIdx.x;
    int s = 0;
#pragma unroll
    for (int j = 0; j < 4; j++) {
        int idx = base + t * 4 + j;
        s += (idx < BINS) ? g_hist[idx] : 0;
    }
    sh[t] = s;
    __syncthreads();
    for (int off = 128; off > 0; off >>= 1) {
        if (t < off) sh[t] += sh[t + off];
        __syncthreads();
    }
    if (t == 0) g_bsum[blockIdx.x] = sh[0];
}
__global__ void scan2_kernel() {    // scan the block sums (tiny)
    if (threadIdx.x == 0) {
        int acc = 0;
        for (int i = 0; i < SCAN_BLOCKS; i++) {
            int v = g_bsum[i];
            g_bsum[i] = acc;
            acc += v;
        }
    }
}
__global__ void scan3_kernel() {    // per-block exclusive scan + offset -> g_hcur
    __shared__ int sh[256];
    int base = blockIdx.x * 1024;
    int t = threadIdx.x;
    int loc[4];
    int s = 0;
#pragma unroll
    for (int j = 0; j < 4; j++) {
        int idx = base + t * 4 + j;
        loc[j] = s;                                   // thread-local exclusive
        s += (idx < BINS) ? g_hist[idx] : 0;
    }
    sh[t] = s;
    __syncthreads();
    // Hillis-Steele inclusive scan over per-thread sums
    for (int off = 1; off < 256; off <<= 1) {
        int v = (t >= off) ? sh[t - off] : 0;
        __syncthreads();
        sh[t] += v;
        __syncthreads();
    }
    int texc = sh[t] - s + g_bsum[blockIdx.x];        // exclusive across threads
#pragma unroll
    for (int j = 0; j < 4; j++) {
        int idx = base + t * 4 + j;
        if (idx < BINS) g_hcur[idx] = texc + loc[j];
    }
}
// placement: pos = cursor[bin]++  (bins avg 2 edges; negligible contention)
__global__ void place_kernel(const int* __restrict__ ei, const int* __restrict__ et) {
    int e = blockIdx.x * blockDim.x + threadIdx.x;
    if (e >= EE) return;
    int src = ei[e];
    int tgt = ei[EE + e];
    int t   = et[e];
    int pos = atomicAdd(&g_hcur[t * NN + src], 1);
    g_epack[pos] = src | (t << 16);
    g_etgt[pos]  = tgt;
}

// -------- edge scatter: warp/edge; edges sorted by (type,src) -> streaming ---
__global__ void scatter_kernel() {
    int w = (blockIdx.x * blockDim.x + threadIdx.x) >> 5;
    if (w >= EE) return;
    int lane = threadIdx.x & 31;
    int p   = g_epack[w];
    int src = p & 0xFFFF;
    int t   = p >> 16;
    int tgt = g_etgt[w];
    float inv = 1.0f / (float)g_deg[tgt * RR + t];
    float4 v = *reinterpret_cast<const float4*>(
        g_xw + ((size_t)t * NN + src) * HF + lane * 4);
    float* dst = g_agg + (size_t)tgt * HF + lane * 4;
    asm volatile("red.global.add.v4.f32 [%0], {%1, %2, %3, %4};"
        :: "l"(__cvta_generic_to_global(dst)),
           "f"(v.x * inv), "f"(v.y * inv), "f"(v.z * inv), "f"(v.w * inv)
        : "memory");
}

// ---------------- BN stats / apply ------------------------------------------
__global__ void bn_stats_kernel() {
    int c = threadIdx.x & 127;
    int rstart = blockIdx.x * (blockDim.x >> 7) + (threadIdx.x >> 7);
    int rstep  = gridDim.x * (blockDim.x >> 7);
    float s = 0.f, ss = 0.f;
    for (int r = rstart; r < NN; r += rstep) {
        float v = g_agg[(size_t)r * HF + c];
        s += v;
        ss += v * v;
    }
    atomicAdd(&g_sum[c], s);
    atomicAdd(&g_sumsq[c], ss);
}
// BN + ReLU, emitting bf16 hi/lo splits (next GEMM A / classifier input)
__global__ void bn_apply_kernel(const float* __restrict__ gamma,
                                const float* __restrict__ beta) {
    int idx = blockIdx.x * blockDim.x + threadIdx.x;
    if (idx >= NN * HF) return;
    int c = idx & 127;
    const float invN = 1.0f / (float)NN;
    float mean = g_sum[c] * invN;
    float var  = fmaxf(g_sumsq[c] * invN - mean * mean, 0.f);
    float v = (g_agg[idx] - mean) * rsqrtf(var + BN_EPS) * gamma[c] + beta[c];
    v = fmaxf(v, 0.f);
    __nv_bfloat16 h = __float2bfloat16_rn(v);
    g_xhi[idx] = h;
    g_xlo[idx] = __float2bfloat16_rn(v - __bfloat162float(h));
}

// ---------------- classifier: out[N,2] = (hi+lo) @ cw + cb ------------------
__global__ void classifier_kernel(const float* __restrict__ cw,
                                  const float* __restrict__ cb,
                                  float* __restrict__ out) {
    __shared__ float wsm[HF * OUTF];
    if (threadIdx.x < HF * OUTF) wsm[threadIdx.x] = cw[threadIdx.x];
    __syncthreads();
    int w = (blockIdx.x * blockDim.x + threadIdx.x) >> 5;
    if (w >= NN) return;
    int lane = threadIdx.x & 31;
    const __nv_bfloat162* ph = reinterpret_cast<const __nv_bfloat162*>(
        g_xhi + (size_t)w * HF + lane * 4);
    const __nv_bfloat162* pl = reinterpret_cast<const __nv_bfloat162*>(
        g_xlo + (size_t)w * HF + lane * 4);
    __nv_bfloat162 h0 = ph[0], h1 = ph[1], l0 = pl[0], l1 = pl[1];
    float vx = __bfloat162float(h0.x) + __bfloat162float(l0.x);
    float vy = __bfloat162float(h0.y) + __bfloat162float(l0.y);
    float vz = __bfloat162float(h1.x) + __bfloat162float(l1.x);
    float vw = __bfloat162float(h1.y) + __bfloat162float(l1.y);
    int c = lane * 4;
    float o0 = vx * wsm[(c + 0) * 2]     + vy * wsm[(c + 1) * 2]
             + vz * wsm[(c + 2) * 2]     + vw * wsm[(c + 3) * 2];
    float o1 = vx * wsm[(c + 0) * 2 + 1] + vy * wsm[(c + 1) * 2 + 1]
             + vz * wsm[(c + 2) * 2 + 1] + vw * wsm[(c + 3) * 2 + 1];
#pragma unroll
    for (int off = 16; off > 0; off >>= 1) {
        o0 += __shfl_down_sync(0xFFFFFFFFu, o0, off);
        o1 += __shfl_down_sync(0xFFFFFFFFu, o1, off);
    }
    if (lane == 0) {
        out[(size_t)w * 2 + 0] = o0 + cb[0];
        out[(size_t)w * 2 + 1] = o1 + cb[1];
    }
}

// ================================ launch =====================================
extern "C" void kernel_launch(void* const* d_in, const int* in_sizes, int n_in,
                              void* d_out, int out_size) {
    const float* x    = (const float*)d_in[0];
    const int*   ei   = (const int*)d_in[1];
    const int*   et   = (const int*)d_in[2];
    const float* w1   = (const float*)d_in[3];
    const float* r1   = (const float*)d_in[4];
    const float* b1   = (const float*)d_in[5];
    const float* g1   = (const float*)d_in[6];
    const float* be1  = (const float*)d_in[7];
    const float* w2   = (const float*)d_in[8];
    const float* r2   = (const float*)d_in[9];
    const float* b2   = (const float*)d_in[10];
    const float* g2   = (const float*)d_in[11];
    const float* be2  = (const float*)d_in[12];
    const float* cw   = (const float*)d_in[13];
    const float* cb   = (const float*)d_in[14];
    float* out = (float*)d_out;

    cudaFuncSetAttribute(gemm_tc_kernel,
                         cudaFuncAttributeMaxDynamicSharedMemorySize, SMEM_BYTES);

    int scatter_blocks  = (EE * 32 + 255) / 256;
    int bn_apply_blocks = (NN * HF + 255) / 256;
    int cls_blocks      = (NN * 32 + 255) / 256;
    int splitx_blocks   = (NN * HF + 255) / 256;
    int splitw_blocks   = (9 * 16384 + 255) / 256;
    int edge_blocks     = (EE + 255) / 256;

    // ---- graph prep (shared by both layers): sort edges by (type, src) ----
    zero_prep_kernel<<<(BINS + 255) / 256, 256>>>();
    deg_hist_kernel<<<edge_blocks, 256>>>(ei, et);
    scan1_kernel<<<SCAN_BLOCKS, 256>>>();
    scan2_kernel<<<1, 32>>>();
    scan3_kernel<<<SCAN_BLOCKS, 256>>>();
    place_kernel<<<edge_blocks, 256>>>(ei, et);

    // ---- layer 1 ----
    split_w_kernel<<<splitw_blocks, 256>>>(w1, r1);
    split_x_kernel<<<splitx_blocks, 256>>>(x);
    gemm_tc_kernel<<<GEMM_TILES, 256, SMEM_BYTES>>>(b1);
    scatter_kernel<<<scatter_blocks, 256>>>();
    bn_stats_kernel<<<256, 256>>>();
    bn_apply_kernel<<<bn_apply_blocks, 256>>>(g1, be1);

    // ---- layer 2 (degree + sorted edges reused) ----
    zero_sums_kernel<<<1, 128>>>();
    split_w_kernel<<<splitw_blocks, 256>>>(w2, r2);
    gemm_tc_kernel<<<GEMM_TILES, 256, SMEM_BYTES>>>(b2);
    scatter_kernel<<<scatter_blocks, 256>>>();
    bn_stats_kernel<<<256, 256>>>();
    bn_apply_kernel<<<bn_apply_blocks, 256>>>(g2, be2);

    // ---- classifier ----
    classifier_kernel<<<cls_blocks, 256>>>(cw, cb, out);
}

// round 8
// speedup vs baseline: 1.3030x; 1.1172x over previous
#include <cuda_runtime.h>
#include <cuda_bf16.h>
#include <cstdint>

#define NN   50000
#define EE   800000
#define INF  128
#define HF   128
#define RR   8
#define OUTF 2
#define BN_EPS 1e-5f
#define GEMM_TILES ((NN + 127) / 128)   // 391
#define BINS (RR * NN)                  // 400000 (type,src) bins
#define SCAN_BLOCKS ((BINS + 1023) / 1024)  // 391

// ---------------- scratch (device globals; no allocation allowed) ----------
__device__ float g_xw[(size_t)RR * NN * HF];        // [R][N][H] transformed
__device__ float g_agg[(size_t)NN * HF];            // pre-BN layer output
__device__ __nv_bfloat16 g_xhi[(size_t)NN * HF];    // bf16 hi split of acts
__device__ __nv_bfloat16 g_xlo[(size_t)NN * HF];    // bf16 lo split
__device__ __nv_bfloat16 g_whi[9 * 128 * 128];      // [mat][n][k] W^T, hi
__device__ __nv_bfloat16 g_wlo[9 * 128 * 128];      // lo
__device__ int   g_deg[NN * RR];
__device__ float g_invdeg[NN * RR];
__device__ float g_sum[HF];
__device__ float g_sumsq[HF];
// edge sorting by (type, src)
__device__ int   g_hist[BINS];      // per-bin counts
__device__ int   g_hcur[BINS];      // scan result -> cursors (end after place)
__device__ int   g_bsum[SCAN_BLOCKS];
__device__ int   g_etgt[EE];        // targets, sorted by (type, src)

// ======================= small helpers ======================================
__device__ __forceinline__ uint32_t smem_to_u32(const void* p) {
    uint32_t a;
    asm("{ .reg .u64 t; cvta.to.shared.u64 t, %1; cvt.u32.u64 %0, t; }"
        : "=r"(a) : "l"(p));
    return a;
}
__device__ __forceinline__ void cp16(uint32_t dst, const void* src) {
    asm volatile("cp.async.cg.shared.global [%0], [%1], 16;"
                 :: "r"(dst), "l"(__cvta_generic_to_global(src)));
}
__device__ __forceinline__ void mma_bf16(float d[4], const uint32_t a[4],
                                         const uint32_t b[2]) {
    asm volatile(
        "mma.sync.aligned.m16n8k16.row.col.f32.bf16.bf16.f32 "
        "{%0,%1,%2,%3}, {%4,%5,%6,%7}, {%8,%9}, {%0,%1,%2,%3};"
        : "+f"(d[0]), "+f"(d[1]), "+f"(d[2]), "+f"(d[3])
        : "r"(a[0]), "r"(a[1]), "r"(a[2]), "r"(a[3]), "r"(b[0]), "r"(b[1]));
}

// =============== SMEM layout (u32 units), stride 68 u32 = 136 bf16 ==========
#define SWU    68
#define AH_U   0
#define AL_U   (128 * SWU)                 // 8704
#define B0_U   (2 * 128 * SWU)             // 17408
#define B1_U   (B0_U + 128 * SWU)          // 26112
#define SMEM_U32S   (B1_U + 128 * SWU)     // 34816
#define SMEM_BYTES  (SMEM_U32S * 4)        // 139264

// prefetch one 128x128 bf16 tile (row-major [n][k]) into padded smem
__device__ __forceinline__ void prefetch_B(uint32_t sb, int bofs_u,
                                           const __nv_bfloat16* W) {
    int tid = threadIdx.x;
#pragma unroll
    for (int i = 0; i < 8; i++) {
        int e = i * 256 + tid;            // 0..2047 uint4s
        int row = e >> 4;                 // 0..127
        int q   = e & 15;                 // uint4 (8 bf16) within row
        cp16(sb + (uint32_t)(bofs_u + row * SWU + q * 4) * 4, W + row * 128 + q * 8);
    }
}

// one bf16 pass: D += A(smem,[m][k]) x B(smem,[n][k])^T over K=128
__device__ __forceinline__ void do_pass(const uint32_t* __restrict__ As,
                                        const uint32_t* __restrict__ Bs,
                                        float d[4][4][4], int wm, int wn,
                                        int lr, int lc) {
#pragma unroll
    for (int ks = 0; ks < 8; ks++) {
        int k0 = ks * 8;                  // u32 offset for k = ks*16
        uint32_t a[4][4], b[4][2];
#pragma unroll
        for (int mt = 0; mt < 4; mt++) {
            const uint32_t* p = As + (wm * 64 + mt * 16 + lr) * SWU + k0 + lc;
            a[mt][0] = p[0];
            a[mt][1] = p[8 * SWU];
            a[mt][2] = p[4];
            a[mt][3] = p[8 * SWU + 4];
        }
#pragma unroll
        for (int nt = 0; nt < 4; nt++) {
            const uint32_t* p = Bs + (wn * 32 + nt * 8 + lr) * SWU + k0 + lc;
            b[nt][0] = p[0];
            b[nt][1] = p[4];
        }
#pragma unroll
        for (int mt = 0; mt < 4; mt++)
#pragma unroll
            for (int nt = 0; nt < 4; nt++) mma_bf16(d[mt][nt], a[mt], b[nt]);
    }
}

// ================== bf16 tensor GEMM: 9 matrices per M-tile =================
__global__ void __launch_bounds__(256, 1) gemm_tc_kernel(const float* __restrict__ bias) {
    extern __shared__ uint32_t smu[];
    uint32_t sb = smem_to_u32(smu);
    const int tid = threadIdx.x;
    const int wid = tid >> 5, lane = tid & 31;
    const int wm = wid & 1, wn = wid >> 1;       // 2 x 4 warp grid (64x32 tiles)
    const int lr = lane >> 2, lc = lane & 3;
    const int m0 = blockIdx.x * 128;

    // A tiles (hi/lo) resident for whole CTA; zero rows past NN
#pragma unroll
    for (int i = 0; i < 8; i++) {
        int e = i * 256 + tid;
        int row = e >> 4, q = e & 15;
        uint32_t dh = sb + (uint32_t)(AH_U + row * SWU + q * 4) * 4;
        uint32_t dl = sb + (uint32_t)(AL_U + row * SWU + q * 4) * 4;
        if (m0 + row < NN) {
            cp16(dh, g_xhi + (size_t)(m0 + row) * 128 + q * 8);
            cp16(dl, g_xlo + (size_t)(m0 + row) * 128 + q * 8);
        } else {
            uint4 z = make_uint4(0, 0, 0, 0);
            *reinterpret_cast<uint4*>(smu + AH_U + row * SWU + q * 4) = z;
            *reinterpret_cast<uint4*>(smu + AL_U + row * SWU + q * 4) = z;
        }
    }
    prefetch_B(sb, B0_U, g_whi);    // B_hi(mat 0)
    asm volatile("cp.async.commit_group;" ::: "memory");
    asm volatile("cp.async.wait_group 0;" ::: "memory");
    __syncthreads();

    float d[4][4][4];
#pragma unroll
    for (int mt = 0; mt < 4; mt++)
#pragma unroll
        for (int nt = 0; nt < 4; nt++)
#pragma unroll
            for (int j = 0; j < 4; j++) d[mt][nt][j] = 0.f;

    const uint32_t* Ah = smu + AH_U;
    const uint32_t* Al = smu + AL_U;
    int stage = 0;
    // 18 tiles: even t = B_hi(t/2) [Ahi & Alo passes], odd t = B_lo(t/2) [Ahi pass]
    for (int t = 0; t < 18; t++) {
        if (t + 1 < 18) {
            int nm = (t + 1) >> 1;
            const __nv_bfloat16* Wn =
                ((t + 1) & 1) ? (g_wlo + nm * 16384) : (g_whi + nm * 16384);
            prefetch_B(sb, stage ? B0_U : B1_U, Wn);
        }
        asm volatile("cp.async.commit_group;" ::: "memory");

        const uint32_t* Bs = smu + (stage ? B1_U : B0_U);
        do_pass(Ah, Bs, d, wm, wn, lr, lc);               // a_hi x b
        if (!(t & 1)) do_pass(Al, Bs, d, wm, wn, lr, lc); // a_lo x b_hi

        if (t & 1) {
            int mat = t >> 1;
            float* gbase = (mat < 8) ? (g_xw + (size_t)mat * NN * HF) : g_agg;
#pragma unroll
            for (int mt = 0; mt < 4; mt++) {
                int r0 = m0 + wm * 64 + mt * 16 + lr;
#pragma unroll
                for (int nt = 0; nt < 4; nt++) {
                    int col = wn * 32 + nt * 8 + lc * 2;
                    float b0 = 0.f, b1 = 0.f;
                    if (mat == 8) { b0 = bias[col]; b1 = bias[col + 1]; }
                    if (r0 < NN)
                        *reinterpret_cast<float2*>(gbase + (size_t)r0 * HF + col) =
                            make_float2(d[mt][nt][0] + b0, d[mt][nt][1] + b1);
                    if (r0 + 8 < NN)
                        *reinterpret_cast<float2*>(gbase + (size_t)(r0 + 8) * HF + col) =
                            make_float2(d[mt][nt][2] + b0, d[mt][nt][3] + b1);
#pragma unroll
                    for (int j = 0; j < 4; j++) d[mt][nt][j] = 0.f;
                }
            }
        }
        asm volatile("cp.async.wait_group 0;" ::: "memory");
        __syncthreads();
        stage ^= 1;
    }
}

// ======================= prep kernels ========================================
__global__ void split_x_kernel(const float* __restrict__ x_in) {
    size_t idx = (size_t)blockIdx.x * blockDim.x + threadIdx.x;
    if (idx >= (size_t)NN * HF) return;
    float v = x_in[idx];
    __nv_bfloat16 h = __float2bfloat16_rn(v);
    g_xhi[idx] = h;
    g_xlo[idx] = __float2bfloat16_rn(v - __bfloat162float(h));
}

// transpose W[mat][k][n] -> [mat][n][k], split hi/lo bf16. mat 8 = root.
__global__ void split_w_kernel(const float* __restrict__ w, const float* __restrict__ root) {
    int idx = blockIdx.x * blockDim.x + threadIdx.x;
    if (idx >= 9 * 16384) return;
    int mat = idx >> 14;
    int n = (idx >> 7) & 127;
    int k = idx & 127;
    float v = (mat < 8) ? w[(mat << 14) + (k << 7) + n] : root[(k << 7) + n];
    __nv_bfloat16 h = __float2bfloat16_rn(v);
    g_whi[idx] = h;
    g_wlo[idx] = __float2bfloat16_rn(v - __bfloat162float(h));
}

// ======================= graph preprocessing =================================
__global__ void zero_prep_kernel() {
    int idx = blockIdx.x * blockDim.x + threadIdx.x;
    if (idx < NN * RR) g_deg[idx] = 0;
    if (idx < BINS) g_hist[idx] = 0;
    if (idx < HF) { g_sum[idx] = 0.f; g_sumsq[idx] = 0.f; }
}
__global__ void zero_sums_kernel() {
    int idx = threadIdx.x;
    if (idx < HF) { g_sum[idx] = 0.f; g_sumsq[idx] = 0.f; }
}
// per-(node,rel) degree + per-(type,src) histogram (both spread; low contention)
__global__ void deg_hist_kernel(const int* __restrict__ ei, const int* __restrict__ et) {
    int e = blockIdx.x * blockDim.x + threadIdx.x;
    if (e >= EE) return;
    int src = ei[e];
    int tgt = ei[EE + e];
    int t   = et[e];
    atomicAdd(&g_deg[tgt * RR + t], 1);
    atomicAdd(&g_hist[t * NN + src], 1);
}
// inv-degree LUT (scatter reads this per edge, warp-uniform)
__global__ void inv_kernel() {
    int i = blockIdx.x * blockDim.x + threadIdx.x;
    if (i < NN * RR) {
        int d = g_deg[i];
        g_invdeg[i] = (d > 0) ? 1.0f / (float)d : 0.f;
    }
}
// --- 3-step exclusive scan over g_hist (400000 bins) -> g_hcur ---------------
__global__ void scan1_kernel() {    // per-1024-bin block sums
    __shared__ int sh[256];
    int base = blockIdx.x * 1024;
    int t = threadIdx.x;
    int s = 0;
#pragma unroll
    for (int j = 0; j < 4; j++) {
        int idx = base + t * 4 + j;
        s += (idx < BINS) ? g_hist[idx] : 0;
    }
    sh[t] = s;
    __syncthreads();
    for (int off = 128; off > 0; off >>= 1) {
        if (t < off) sh[t] += sh[t + off];
        __syncthreads();
    }
    if (t == 0) g_bsum[blockIdx.x] = sh[0];
}
__global__ void scan2_kernel() {    // 512-thread Hillis-Steele over block sums
    __shared__ int sh[512];
    int t = threadIdx.x;
    int v = (t < SCAN_BLOCKS) ? g_bsum[t] : 0;
    sh[t] = v;
    __syncthreads();
    for (int off = 1; off < 512; off <<= 1) {
        int u = (t >= off) ? sh[t - off] : 0;
        __syncthreads();
        sh[t] += u;
        __syncthreads();
    }
    if (t < SCAN_BLOCKS) g_bsum[t] = sh[t] - v;   // exclusive
}
__global__ void scan3_kernel() {    // per-block exclusive scan + offset -> g_hcur
    __shared__ int sh[256];
    int base = blockIdx.x * 1024;
    int t = threadIdx.x;
    int loc[4];
    int s = 0;
#pragma unroll
    for (int j = 0; j < 4; j++) {
        int idx = base + t * 4 + j;
        loc[j] = s;                                   // thread-local exclusive
        s += (idx < BINS) ? g_hist[idx] : 0;
    }
    sh[t] = s;
    __syncthreads();
    for (int off = 1; off < 256; off <<= 1) {
        int v = (t >= off) ? sh[t - off] : 0;
        __syncthreads();
        sh[t] += v;
        __syncthreads();
    }
    int texc = sh[t] - s + g_bsum[blockIdx.x];        // exclusive across threads
#pragma unroll
    for (int j = 0; j < 4; j++) {
        int idx = base + t * 4 + j;
        if (idx < BINS) g_hcur[idx] = texc + loc[j];
    }
}
// placement: pos = cursor[bin]++ ; store target only
__global__ void place_kernel(const int* __restrict__ ei, const int* __restrict__ et) {
    int e = blockIdx.x * blockDim.x + threadIdx.x;
    if (e >= EE) return;
    int src = ei[e];
    int tgt = ei[EE + e];
    int t   = et[e];
    int pos = atomicAdd(&g_hcur[t * NN + src], 1);
    g_etgt[pos] = tgt;
}

// -------- bin scatter: one warp per (type,src) bin; gather once, red per tgt -
__global__ void scatter_kernel() {
    int b = (blockIdx.x * blockDim.x + threadIdx.x) >> 5;   // bin id
    if (b >= BINS) return;
    int cnt = g_hist[b];
    if (cnt == 0) return;
    int lane = threadIdx.x & 31;
    int end   = g_hcur[b];          // cursor advanced to bin end by place
    int start = end - cnt;
    int t   = b / NN;
    int src = b - t * NN;
    float4 v = *reinterpret_cast<const float4*>(
        g_xw + ((size_t)t * NN + src) * HF + lane * 4);
    for (int i = start; i < end; i++) {
        int tgt = __ldg(&g_etgt[i]);
        float inv = __ldg(&g_invdeg[tgt * RR + t]);
        float* dst = g_agg + (size_t)tgt * HF + lane * 4;
        asm volatile("red.global.add.v4.f32 [%0], {%1, %2, %3, %4};"
            :: "l"(__cvta_generic_to_global(dst)),
               "f"(v.x * inv), "f"(v.y * inv), "f"(v.z * inv), "f"(v.w * inv)
            : "memory");
    }
}

// ---------------- BN stats / apply ------------------------------------------
__global__ void bn_stats_kernel() {
    int c = threadIdx.x & 127;
    int rstart = blockIdx.x * (blockDim.x >> 7) + (threadIdx.x >> 7);
    int rstep  = gridDim.x * (blockDim.x >> 7);
    float s = 0.f, ss = 0.f;
    for (int r = rstart; r < NN; r += rstep) {
        float v = g_agg[(size_t)r * HF + c];
        s += v;
        ss += v * v;
    }
    atomicAdd(&g_sum[c], s);
    atomicAdd(&g_sumsq[c], ss);
}
// BN + ReLU, emitting bf16 hi/lo splits (next GEMM A / classifier input)
__global__ void bn_apply_kernel(const float* __restrict__ gamma,
                                const float* __restrict__ beta) {
    int idx = blockIdx.x * blockDim.x + threadIdx.x;
    if (idx >= NN * HF) return;
    int c = idx & 127;
    const float invN = 1.0f / (float)NN;
    float mean = g_sum[c] * invN;
    float var  = fmaxf(g_sumsq[c] * invN - mean * mean, 0.f);
    float v = (g_agg[idx] - mean) * rsqrtf(var + BN_EPS) * gamma[c] + beta[c];
    v = fmaxf(v, 0.f);
    __nv_bfloat16 h = __float2bfloat16_rn(v);
    g_xhi[idx] = h;
    g_xlo[idx] = __float2bfloat16_rn(v - __bfloat162float(h));
}

// ---------------- classifier: out[N,2] = (hi+lo) @ cw + cb ------------------
__global__ void classifier_kernel(const float* __restrict__ cw,
                                  const float* __restrict__ cb,
                                  float* __restrict__ out) {
    __shared__ float wsm[HF * OUTF];
    if (threadIdx.x < HF * OUTF) wsm[threadIdx.x] = cw[threadIdx.x];
    __syncthreads();
    int w = (blockIdx.x * blockDim.x + threadIdx.x) >> 5;
    if (w >= NN) return;
    int lane = threadIdx.x & 31;
    const __nv_bfloat162* ph = reinterpret_cast<const __nv_bfloat162*>(
        g_xhi + (size_t)w * HF + lane * 4);
    const __nv_bfloat162* pl = reinterpret_cast<const __nv_bfloat162*>(
        g_xlo + (size_t)w * HF + lane * 4);
    __nv_bfloat162 h0 = ph[0], h1 = ph[1], l0 = pl[0], l1 = pl[1];
    float vx = __bfloat162float(h0.x) + __bfloat162float(l0.x);
    float vy = __bfloat162float(h0.y) + __bfloat162float(l0.y);
    float vz = __bfloat162float(h1.x) + __bfloat162float(l1.x);
    float vw = __bfloat162float(h1.y) + __bfloat162float(l1.y);
    int c = lane * 4;
    float o0 = vx * wsm[(c + 0) * 2]     + vy * wsm[(c + 1) * 2]
             + vz * wsm[(c + 2) * 2]     + vw * wsm[(c + 3) * 2];
    float o1 = vx * wsm[(c + 0) * 2 + 1] + vy * wsm[(c + 1) * 2 + 1]
             + vz * wsm[(c + 2) * 2 + 1] + vw * wsm[(c + 3) * 2 + 1];
#pragma unroll
    for (int off = 16; off > 0; off >>= 1) {
        o0 += __shfl_down_sync(0xFFFFFFFFu, o0, off);
        o1 += __shfl_down_sync(0xFFFFFFFFu, o1, off);
    }
    if (lane == 0) {
        out[(size_t)w * 2 + 0] = o0 + cb[0];
        out[(size_t)w * 2 + 1] = o1 + cb[1];
    }
}

// ================================ launch =====================================
extern "C" void kernel_launch(void* const* d_in, const int* in_sizes, int n_in,
                              void* d_out, int out_size) {
    const float* x    = (const float*)d_in[0];
    const int*   ei   = (const int*)d_in[1];
    const int*   et   = (const int*)d_in[2];
    const float* w1   = (const float*)d_in[3];
    const float* r1   = (const float*)d_in[4];
    const float* b1   = (const float*)d_in[5];
    const float* g1   = (const float*)d_in[6];
    const float* be1  = (const float*)d_in[7];
    const float* w2   = (const float*)d_in[8];
    const float* r2   = (const float*)d_in[9];
    const float* b2   = (const float*)d_in[10];
    const float* g2   = (const float*)d_in[11];
    const float* be2  = (const float*)d_in[12];
    const float* cw   = (const float*)d_in[13];
    const float* cb   = (const float*)d_in[14];
    float* out = (float*)d_out;

    cudaFuncSetAttribute(gemm_tc_kernel,
                         cudaFuncAttributeMaxDynamicSharedMemorySize, SMEM_BYTES);

    int scatter_blocks  = (BINS * 32 + 255) / 256;   // warp per bin
    int bn_apply_blocks = (NN * HF + 255) / 256;
    int cls_blocks      = (NN * 32 + 255) / 256;
    int splitx_blocks   = (NN * HF + 255) / 256;
    int splitw_blocks   = (9 * 16384 + 255) / 256;
    int edge_blocks     = (EE + 255) / 256;

    // ---- graph prep (shared by both layers): sort edges by (type, src) ----
    zero_prep_kernel<<<(BINS + 255) / 256, 256>>>();
    deg_hist_kernel<<<edge_blocks, 256>>>(ei, et);
    inv_kernel<<<(NN * RR + 255) / 256, 256>>>();
    scan1_kernel<<<SCAN_BLOCKS, 256>>>();
    scan2_kernel<<<1, 512>>>();
    scan3_kernel<<<SCAN_BLOCKS, 256>>>();
    place_kernel<<<edge_blocks, 256>>>(ei, et);

    // ---- layer 1 ----
    split_w_kernel<<<splitw_blocks, 256>>>(w1, r1);
    split_x_kernel<<<splitx_blocks, 256>>>(x);
    gemm_tc_kernel<<<GEMM_TILES, 256, SMEM_BYTES>>>(b1);
    scatter_kernel<<<scatter_blocks, 256>>>();
    bn_stats_kernel<<<256, 256>>>();
    bn_apply_kernel<<<bn_apply_blocks, 256>>>(g1, be1);

    // ---- layer 2 (degree + sorted edges reused) ----
    zero_sums_kernel<<<1, 128>>>();
    split_w_kernel<<<splitw_blocks, 256>>>(w2, r2);
    gemm_tc_kernel<<<GEMM_TILES, 256, SMEM_BYTES>>>(b2);
    scatter_kernel<<<scatter_blocks, 256>>>();
    bn_stats_kernel<<<256, 256>>>();
    bn_apply_kernel<<<bn_apply_blocks, 256>>>(g2, be2);

    // ---- classifier ----
    classifier_kernel<<<cls_blocks, 256>>>(cw, cb, out);
}

// round 9
// speedup vs baseline: 1.3522x; 1.0378x over previous
#include <cuda_runtime.h>
#include <cuda_bf16.h>
#include <cstdint>

#define NN   50000
#define EE   800000
#define INF  128
#define HF   128
#define RR   8
#define OUTF 2
#define BN_EPS 1e-5f
#define GEMM_TILES ((NN + 127) / 128)   // 391
#define BINS (RR * NN)                  // 400000 (type,src) bins
#define SCAN_BLOCKS ((BINS + 1023) / 1024)  // 391

// ---------------- scratch (device globals; no allocation allowed) ----------
__device__ float g_xw[(size_t)RR * NN * HF];        // [R][N][H] transformed
__device__ float g_agg[(size_t)NN * HF];            // pre-BN layer output
__device__ __nv_bfloat16 g_xhi[(size_t)NN * HF];    // bf16 hi split of acts
__device__ __nv_bfloat16 g_xlo[(size_t)NN * HF];    // bf16 lo split
__device__ __nv_bfloat16 g_whi[9 * 128 * 128];      // [mat][n][k] W^T, hi
__device__ __nv_bfloat16 g_wlo[9 * 128 * 128];      // lo
__device__ int   g_deg[NN * RR];
__device__ float g_invdeg[NN * RR];
__device__ float g_sum[HF];
__device__ float g_sumsq[HF];
// edge sorting by (type, src)
__device__ int   g_hist[BINS];      // per-bin counts
__device__ int   g_hcur[BINS];      // scan result -> cursors (end after place)
__device__ int   g_bsum[SCAN_BLOCKS];
__device__ int   g_etgt[EE];        // targets, sorted by (type, src)

// ======================= small helpers ======================================
__device__ __forceinline__ uint32_t smem_to_u32(const void* p) {
    uint32_t a;
    asm("{ .reg .u64 t; cvta.to.shared.u64 t, %1; cvt.u32.u64 %0, t; }"
        : "=r"(a) : "l"(p));
    return a;
}
__device__ __forceinline__ void cp16(uint32_t dst, const void* src) {
    asm volatile("cp.async.cg.shared.global [%0], [%1], 16;"
                 :: "r"(dst), "l"(__cvta_generic_to_global(src)));
}
__device__ __forceinline__ void mma_bf16(float d[4], const uint32_t a[4],
                                         uint32_t b0, uint32_t b1) {
    asm volatile(
        "mma.sync.aligned.m16n8k16.row.col.f32.bf16.bf16.f32 "
        "{%0,%1,%2,%3}, {%4,%5,%6,%7}, {%8,%9}, {%0,%1,%2,%3};"
        : "+f"(d[0]), "+f"(d[1]), "+f"(d[2]), "+f"(d[3])
        : "r"(a[0]), "r"(a[1]), "r"(a[2]), "r"(a[3]), "r"(b0), "r"(b1));
}
__device__ __forceinline__ void ldsm_x4(uint32_t r[4], uint32_t addr) {
    asm volatile("ldmatrix.sync.aligned.m8n8.x4.shared.b16 {%0,%1,%2,%3}, [%4];"
        : "=r"(r[0]), "=r"(r[1]), "=r"(r[2]), "=r"(r[3]) : "r"(addr));
}

// =============== SMEM layout (u32 units), stride 68 u32 = 136 bf16 ==========
#define SWU    68
#define ROWB   (SWU * 4)                   // 272 bytes per row
#define AH_U   0
#define AL_U   (128 * SWU)                 // 8704
#define B0_U   (2 * 128 * SWU)             // 17408
#define B1_U   (B0_U + 128 * SWU)          // 26112
#define SMEM_U32S   (B1_U + 128 * SWU)     // 34816
#define SMEM_BYTES  (SMEM_U32S * 4)        // 139264

// prefetch one 128x128 bf16 tile (row-major [n][k]) into padded smem
__device__ __forceinline__ void prefetch_B(uint32_t sb, int bofs_u,
                                           const __nv_bfloat16* W) {
    int tid = threadIdx.x;
#pragma unroll
    for (int i = 0; i < 8; i++) {
        int e = i * 256 + tid;            // 0..2047 uint4s
        int row = e >> 4;                 // 0..127
        int q   = e & 15;                 // uint4 (8 bf16) within row
        cp16(sb + (uint32_t)(bofs_u + row * SWU + q * 4) * 4, W + row * 128 + q * 8);
    }
}

// one bf16 pass via ldmatrix: D += A x B^T over K=128.
// aBase/bBase are smem BYTE addresses of the tile origins.
// aLane/bLane are per-thread lane offsets (precomputed).
__device__ __forceinline__ void do_pass(uint32_t aBase, uint32_t bBase,
                                        uint32_t aLane, uint32_t bLane,
                                        float d[4][4][4]) {
#pragma unroll
    for (int ks = 0; ks < 8; ks++) {
        uint32_t kb = (uint32_t)ks * 32;          // 16 bf16 = 32 bytes
        uint32_t a[4][4];
#pragma unroll
        for (int mt = 0; mt < 4; mt++)
            ldsm_x4(a[mt], aBase + aLane + (uint32_t)(mt * 16) * ROWB + kb);
#pragma unroll
        for (int p = 0; p < 2; p++) {
            uint32_t b[4];
            ldsm_x4(b, bBase + bLane + (uint32_t)(p * 16) * ROWB + kb);
#pragma unroll
            for (int mt = 0; mt < 4; mt++) {
                mma_bf16(d[mt][2 * p],     a[mt], b[0], b[1]);
                mma_bf16(d[mt][2 * p + 1], a[mt], b[2], b[3]);
            }
        }
    }
}

// ================== bf16 tensor GEMM: 9 matrices per M-tile =================
__global__ void __launch_bounds__(256, 1) gemm_tc_kernel(const float* __restrict__ bias) {
    extern __shared__ uint32_t smu[];
    uint32_t sb = smem_to_u32(smu);
    const int tid = threadIdx.x;
    const int wid = tid >> 5, lane = tid & 31;
    const int wm = wid & 1, wn = wid >> 1;       // 2 x 4 warp grid (64x32 tiles)
    const int lr = lane >> 2, lc = lane & 3;
    const int m0 = blockIdx.x * 128;

    // lane offsets for ldmatrix (bytes):
    // A: row = wm*64 + (lane&15) (+mt*16), k-half = lane>>4
    const uint32_t aLane = (uint32_t)(wm * 64 + (lane & 15)) * ROWB
                         + (uint32_t)(lane >> 4) * 16;
    // B: n row = wn*32 + ((lane>>4)&1)*8 + (lane&7) (+p*16), k-half = (lane>>3)&1
    const uint32_t bLane = (uint32_t)(wn * 32 + ((lane >> 4) & 1) * 8 + (lane & 7)) * ROWB
                         + (uint32_t)((lane >> 3) & 1) * 16;

    // A tiles (hi/lo) resident for whole CTA; zero rows past NN
#pragma unroll
    for (int i = 0; i < 8; i++) {
        int e = i * 256 + tid;
        int row = e >> 4, q = e & 15;
        uint32_t dh = sb + (uint32_t)(AH_U + row * SWU + q * 4) * 4;
        uint32_t dl = sb + (uint32_t)(AL_U + row * SWU + q * 4) * 4;
        if (m0 + row < NN) {
            cp16(dh, g_xhi + (size_t)(m0 + row) * 128 + q * 8);
            cp16(dl, g_xlo + (size_t)(m0 + row) * 128 + q * 8);
        } else {
            uint4 z = make_uint4(0, 0, 0, 0);
            *reinterpret_cast<uint4*>(smu + AH_U + row * SWU + q * 4) = z;
            *reinterpret_cast<uint4*>(smu + AL_U + row * SWU + q * 4) = z;
        }
    }
    prefetch_B(sb, B0_U, g_whi);    // B_hi(mat 0)
    asm volatile("cp.async.commit_group;" ::: "memory");
    asm volatile("cp.async.wait_group 0;" ::: "memory");
    __syncthreads();

    float d[4][4][4];
#pragma unroll
    for (int mt = 0; mt < 4; mt++)
#pragma unroll
        for (int nt = 0; nt < 4; nt++)
#pragma unroll
            for (int j = 0; j < 4; j++) d[mt][nt][j] = 0.f;

    const uint32_t ahB = sb + AH_U * 4;
    const uint32_t alB = sb + AL_U * 4;
    int stage = 0;
    // 18 tiles: even t = B_hi(t/2) [Ahi & Alo passes], odd t = B_lo(t/2) [Ahi pass]
    for (int t = 0; t < 18; t++) {
        if (t + 1 < 18) {
            int nm = (t + 1) >> 1;
            const __nv_bfloat16* Wn =
                ((t + 1) & 1) ? (g_wlo + nm * 16384) : (g_whi + nm * 16384);
            prefetch_B(sb, stage ? B0_U : B1_U, Wn);
        }
        asm volatile("cp.async.commit_group;" ::: "memory");

        const uint32_t bB = sb + (stage ? B1_U : B0_U) * 4;
        do_pass(ahB, bB, aLane, bLane, d);                  // a_hi x b
        if (!(t & 1)) do_pass(alB, bB, aLane, bLane, d);    // a_lo x b_hi

        if (t & 1) {
            int mat = t >> 1;
            float* gbase = (mat < 8) ? (g_xw + (size_t)mat * NN * HF) : g_agg;
#pragma unroll
            for (int mt = 0; mt < 4; mt++) {
                int r0 = m0 + wm * 64 + mt * 16 + lr;
#pragma unroll
                for (int nt = 0; nt < 4; nt++) {
                    int col = wn * 32 + nt * 8 + lc * 2;
                    float b0 = 0.f, b1 = 0.f;
                    if (mat == 8) { b0 = bias[col]; b1 = bias[col + 1]; }
                    if (r0 < NN)
                        *reinterpret_cast<float2*>(gbase + (size_t)r0 * HF + col) =
                            make_float2(d[mt][nt][0] + b0, d[mt][nt][1] + b1);
                    if (r0 + 8 < NN)
                        *reinterpret_cast<float2*>(gbase + (size_t)(r0 + 8) * HF + col) =
                            make_float2(d[mt][nt][2] + b0, d[mt][nt][3] + b1);
#pragma unroll
                    for (int j = 0; j < 4; j++) d[mt][nt][j] = 0.f;
                }
            }
        }
        asm volatile("cp.async.wait_group 0;" ::: "memory");
        __syncthreads();
        stage ^= 1;
    }
}

// ======================= prep kernels ========================================
__global__ void split_x_kernel(const float* __restrict__ x_in) {
    size_t idx = (size_t)blockIdx.x * blockDim.x + threadIdx.x;
    if (idx >= (size_t)NN * HF) return;
    float v = x_in[idx];
    __nv_bfloat16 h = __float2bfloat16_rn(v);
    g_xhi[idx] = h;
    g_xlo[idx] = __float2bfloat16_rn(v - __bfloat162float(h));
}

// transpose W[mat][k][n] -> [mat][n][k], split hi/lo bf16. mat 8 = root.
__global__ void split_w_kernel(const float* __restrict__ w, const float* __restrict__ root) {
    int idx = blockIdx.x * blockDim.x + threadIdx.x;
    if (idx >= 9 * 16384) return;
    int mat = idx >> 14;
    int n = (idx >> 7) & 127;
    int k = idx & 127;
    float v = (mat < 8) ? w[(mat << 14) + (k << 7) + n] : root[(k << 7) + n];
    __nv_bfloat16 h = __float2bfloat16_rn(v);
    g_whi[idx] = h;
    g_wlo[idx] = __float2bfloat16_rn(v - __bfloat162float(h));
}

// ======================= graph preprocessing =================================
__global__ void zero_prep_kernel() {
    int idx = blockIdx.x * blockDim.x + threadIdx.x;
    if (idx < NN * RR) g_deg[idx] = 0;
    if (idx < BINS) g_hist[idx] = 0;
    if (idx < HF) { g_sum[idx] = 0.f; g_sumsq[idx] = 0.f; }
}
__global__ void zero_sums_kernel() {
    int idx = threadIdx.x;
    if (idx < HF) { g_sum[idx] = 0.f; g_sumsq[idx] = 0.f; }
}
// per-(node,rel) degree + per-(type,src) histogram (both spread; low contention)
__global__ void deg_hist_kernel(const int* __restrict__ ei, const int* __restrict__ et) {
    int e = blockIdx.x * blockDim.x + threadIdx.x;
    if (e >= EE) return;
    int src = ei[e];
    int tgt = ei[EE + e];
    int t   = et[e];
    atomicAdd(&g_deg[tgt * RR + t], 1);
    atomicAdd(&g_hist[t * NN + src], 1);
}
// --- scan over g_hist (400000 bins) -> g_hcur; also computes inv-degree LUT --
__global__ void scan1_kernel() {    // per-1024-bin block sums (+ invdeg fused)
    __shared__ int sh[256];
    int base = blockIdx.x * 1024;
    int t = threadIdx.x;
    int s = 0;
#pragma unroll
    for (int j = 0; j < 4; j++) {
        int idx = base + t * 4 + j;
        if (idx < BINS) {
            s += g_hist[idx];
            int dg = g_deg[idx];      // same element count (NN*RR == BINS)
            g_invdeg[idx] = (dg > 0) ? 1.0f / (float)dg : 0.f;
        }
    }
    sh[t] = s;
    __syncthreads();
    for (int off = 128; off > 0; off >>= 1) {
        if (t < off) sh[t] += sh[t + off];
        __syncthreads();
    }
    if (t == 0) g_bsum[blockIdx.x] = sh[0];
}
__global__ void scan2_kernel() {    // 512-thread Hillis-Steele over block sums
    __shared__ int sh[512];
    int t = threadIdx.x;
    int v = (t < SCAN_BLOCKS) ? g_bsum[t] : 0;
    sh[t] = v;
    __syncthreads();
    for (int off = 1; off < 512; off <<= 1) {
        int u = (t >= off) ? sh[t - off] : 0;
        __syncthreads();
        sh[t] += u;
        __syncthreads();
    }
    if (t < SCAN_BLOCKS) g_bsum[t] = sh[t] - v;   // exclusive
}
__global__ void scan3_kernel() {    // per-block exclusive scan + offset -> g_hcur
    __shared__ int sh[256];
    int base = blockIdx.x * 1024;
    int t = threadIdx.x;
    int loc[4];
    int s = 0;
#pragma unroll
    for (int j = 0; j < 4; j++) {
        int idx = base + t * 4 + j;
        loc[j] = s;                                   // thread-local exclusive
        s += (idx < BINS) ? g_hist[idx] : 0;
    }
    sh[t] = s;
    __syncthreads();
    for (int off = 1; off < 256; off <<= 1) {
        int v = (t >= off) ? sh[t - off] : 0;
        __syncthreads();
        sh[t] += v;
        __syncthreads();
    }
    int texc = sh[t] - s + g_bsum[blockIdx.x];        // exclusive across threads
#pragma unroll
    for (int j = 0; j < 4; j++) {
        int idx = base + t * 4 + j;
        if (idx < BINS) g_hcur[idx] = texc + loc[j];
    }
}
// placement: pos = cursor[bin]++ ; store target only
__global__ void place_kernel(const int* __restrict__ ei, const int* __restrict__ et) {
    int e = blockIdx.x * blockDim.x + threadIdx.x;
    if (e >= EE) return;
    int src = ei[e];
    int tgt = ei[EE + e];
    int t   = et[e];
    int pos = atomicAdd(&g_hcur[t * NN + src], 1);
    g_etgt[pos] = tgt;
}

// -------- bin scatter: one warp per (type,src) bin; gather once, red per tgt -
__global__ void scatter_kernel() {
    int b = (blockIdx.x * blockDim.x + threadIdx.x) >> 5;   // bin id
    if (b >= BINS) return;
    int cnt = g_hist[b];
    if (cnt == 0) return;
    int lane = threadIdx.x & 31;
    int end   = g_hcur[b];          // cursor advanced to bin end by place
    int start = end - cnt;
    int t   = b / NN;
    int src = b - t * NN;
    float4 v = *reinterpret_cast<const float4*>(
        g_xw + ((size_t)t * NN + src) * HF + lane * 4);
    for (int i = start; i < end; i++) {
        int tgt = __ldg(&g_etgt[i]);
        float inv = __ldg(&g_invdeg[tgt * RR + t]);
        float* dst = g_agg + (size_t)tgt * HF + lane * 4;
        asm volatile("red.global.add.v4.f32 [%0], {%1, %2, %3, %4};"
            :: "l"(__cvta_generic_to_global(dst)),
               "f"(v.x * inv), "f"(v.y * inv), "f"(v.z * inv), "f"(v.w * inv)
            : "memory");
    }
}

// ---------------- BN stats / apply ------------------------------------------
__global__ void bn_stats_kernel() {
    int c = threadIdx.x & 127;
    int rstart = blockIdx.x * (blockDim.x >> 7) + (threadIdx.x >> 7);
    int rstep  = gridDim.x * (blockDim.x >> 7);
    float s = 0.f, ss = 0.f;
    for (int r = rstart; r < NN; r += rstep) {
        float v = g_agg[(size_t)r * HF + c];
        s += v;
        ss += v * v;
    }
    atomicAdd(&g_sum[c], s);
    atomicAdd(&g_sumsq[c], ss);
}
// BN + ReLU, emitting bf16 hi/lo splits (next GEMM A / classifier input)
__global__ void bn_apply_kernel(const float* __restrict__ gamma,
                                const float* __restrict__ beta) {
    int idx = blockIdx.x * blockDim.x + threadIdx.x;
    if (idx >= NN * HF) return;
    int c = idx & 127;
    const float invN = 1.0f / (float)NN;
    float mean = g_sum[c] * invN;
    float var  = fmaxf(g_sumsq[c] * invN - mean * mean, 0.f);
    float v = (g_agg[idx] - mean) * rsqrtf(var + BN_EPS) * gamma[c] + beta[c];
    v = fmaxf(v, 0.f);
    __nv_bfloat16 h = __float2bfloat16_rn(v);
    g_xhi[idx] = h;
    g_xlo[idx] = __float2bfloat16_rn(v - __bfloat162float(h));
}

// ---------------- classifier: out[N,2] = (hi+lo) @ cw + cb ------------------
__global__ void classifier_kernel(const float* __restrict__ cw,
                                  const float* __restrict__ cb,
                                  float* __restrict__ out) {
    __shared__ float wsm[HF * OUTF];
    if (threadIdx.x < HF * OUTF) wsm[threadIdx.x] = cw[threadIdx.x];
    __syncthreads();
    int w = (blockIdx.x * blockDim.x + threadIdx.x) >> 5;
    if (w >= NN) return;
    int lane = threadIdx.x & 31;
    const __nv_bfloat162* ph = reinterpret_cast<const __nv_bfloat162*>(
        g_xhi + (size_t)w * HF + lane * 4);
    const __nv_bfloat162* pl = reinterpret_cast<const __nv_bfloat162*>(
        g_xlo + (size_t)w * HF + lane * 4);
    __nv_bfloat162 h0 = ph[0], h1 = ph[1], l0 = pl[0], l1 = pl[1];
    float vx = __bfloat162float(h0.x) + __bfloat162float(l0.x);
    float vy = __bfloat162float(h0.y) + __bfloat162float(l0.y);
    float vz = __bfloat162float(h1.x) + __bfloat162float(l1.x);
    float vw = __bfloat162float(h1.y) + __bfloat162float(l1.y);
    int c = lane * 4;
    float o0 = vx * wsm[(c + 0) * 2]     + vy * wsm[(c + 1) * 2]
             + vz * wsm[(c + 2) * 2]     + vw * wsm[(c + 3) * 2];
    float o1 = vx * wsm[(c + 0) * 2 + 1] + vy * wsm[(c + 1) * 2 + 1]
             + vz * wsm[(c + 2) * 2 + 1] + vw * wsm[(c + 3) * 2 + 1];
#pragma unroll
    for (int off = 16; off > 0; off >>= 1) {
        o0 += __shfl_down_sync(0xFFFFFFFFu, o0, off);
        o1 += __shfl_down_sync(0xFFFFFFFFu, o1, off);
    }
    if (lane == 0) {
        out[(size_t)w * 2 + 0] = o0 + cb[0];
        out[(size_t)w * 2 + 1] = o1 + cb[1];
    }
}

// ================================ launch =====================================
extern "C" void kernel_launch(void* const* d_in, const int* in_sizes, int n_in,
                              void* d_out, int out_size) {
    const float* x    = (const float*)d_in[0];
    const int*   ei   = (const int*)d_in[1];
    const int*   et   = (const int*)d_in[2];
    const float* w1   = (const float*)d_in[3];
    const float* r1   = (const float*)d_in[4];
    const float* b1   = (const float*)d_in[5];
    const float* g1   = (const float*)d_in[6];
    const float* be1  = (const float*)d_in[7];
    const float* w2   = (const float*)d_in[8];
    const float* r2   = (const float*)d_in[9];
    const float* b2   = (const float*)d_in[10];
    const float* g2   = (const float*)d_in[11];
    const float* be2  = (const float*)d_in[12];
    const float* cw   = (const float*)d_in[13];
    const float* cb   = (const float*)d_in[14];
    float* out = (float*)d_out;

    cudaFuncSetAttribute(gemm_tc_kernel,
                         cudaFuncAttributeMaxDynamicSharedMemorySize, SMEM_BYTES);

    int scatter_blocks  = (BINS * 32 + 255) / 256;   // warp per bin
    int bn_apply_blocks = (NN * HF + 255) / 256;
    int cls_blocks      = (NN * 32 + 255) / 256;
    int splitx_blocks   = (NN * HF + 255) / 256;
    int splitw_blocks   = (9 * 16384 + 255) / 256;
    int edge_blocks     = (EE + 255) / 256;

    // Launch order puts gemm_tc_kernel at launch #6 (ncu captures -s 5 -c 1).
    // 1-2: weight/activation splits (independent of graph prep)
    split_w_kernel<<<splitw_blocks, 256>>>(w1, r1);
    split_x_kernel<<<splitx_blocks, 256>>>(x);
    // 3-5: graph prep first half
    zero_prep_kernel<<<(BINS + 255) / 256, 256>>>();
    deg_hist_kernel<<<edge_blocks, 256>>>(ei, et);
    scan1_kernel<<<SCAN_BLOCKS, 256>>>();            // + fused invdeg
    // 6: layer-1 GEMM  <-- profiled launch
    gemm_tc_kernel<<<GEMM_TILES, 256, SMEM_BYTES>>>(b1);
    // 7-9: graph prep second half (needed only by scatter)
    scan2_kernel<<<1, 512>>>();
    scan3_kernel<<<SCAN_BLOCKS, 256>>>();
    place_kernel<<<edge_blocks, 256>>>(ei, et);
    // 10+: layer-1 rest
    scatter_kernel<<<scatter_blocks, 256>>>();
    bn_stats_kernel<<<256, 256>>>();
    bn_apply_kernel<<<bn_apply_blocks, 256>>>(g1, be1);

    // ---- layer 2 (degree + sorted edges reused) ----
    zero_sums_kernel<<<1, 128>>>();
    split_w_kernel<<<splitw_blocks, 256>>>(w2, r2);
    gemm_tc_kernel<<<GEMM_TILES, 256, SMEM_BYTES>>>(b2);
    scatter_kernel<<<scatter_blocks, 256>>>();
    bn_stats_kernel<<<256, 256>>>();
    bn_apply_kernel<<<bn_apply_blocks, 256>>>(g2, be2);

    // ---- classifier ----
    classifier_kernel<<<cls_blocks, 256>>>(cw, cb, out);
}